// round 14
// baseline (speedup 1.0000x reference)
#include <cuda_runtime.h>
#include <cuda_fp16.h>
#include <cstdint>

// ---------------------------------------------------------------------------
// Bahdanau additive attention, B=32, T=2048, H=C=1024.
// R14 (base = R13, 445.3us; GEMM untouched at 297us/tensor=76%): launch
// consolidation to 3 kernels using R8-verified pieces:
//  1. prep = convert + transpose + dp_part + zero-scores (block ranges)
//  2. GEMM folds dp_reduce into its kt==0 sdp load (bias + 4 partials)
//  3. softmax fused into context (per-block max/sum over the batch's scores)
// R8 post-mortem: its regression was __launch_bounds__(256,2) reg-spill in
// the 8-warp GEMM, NOT the fusion — fusions are safe.
// ---------------------------------------------------------------------------

#define B_DIM 32
#define T_DIM 2048
#define H_DIM 1024
#define C_DIM 1024
#define M_TOTAL (B_DIM * T_DIM)      // 65536

#define CTA_M 128
#define N_CHUNK 128
#define NUM_NC (C_DIM / N_CHUNK)     // 8
#define K_STAGE 64
#define NUM_KT (H_DIM / K_STAGE)     // 16
#define NUM_MTILES (M_TOTAL / CTA_M) // 512
#define NUM_UNITS (NUM_MTILES * 4)   // 2048 (mtile x nc-pair)
#define GEMM_CTAS 296                // 2 per SM x 148
#define GEMM_THREADS 128             // 4 warps: 2(M) x 2(N), warp tile 64x64

#define STAGE_BYTES 32768            // A 16KB + B 16KB
#define NSTAGES 3
#define OFF_MBAR (NSTAGES * STAGE_BYTES)   // full[3] at +0, empty[3] at +32
#define OFF_DP (OFF_MBAR + 64)             // 2 x 128 f (double-buffered)
#define OFF_W (OFF_DP + 1024)              // 2 x 128 f
#define OFF_RED (OFF_W + 1024)             // 128 f
#define SMEM_TOTAL (OFF_RED + 512)         // 100928 (x2 CTA/SM = 201856 <= 227KB)

// prep block ranges
#define PREP_CONV_BLOCKS 16384
#define PREP_TRANS_BLOCKS 1024
#define PREP_DP_BLOCKS 32
#define PREP_ZERO_BLOCKS 32
#define PREP_BLOCKS (PREP_CONV_BLOCKS + PREP_TRANS_BLOCKS + PREP_DP_BLOCKS + PREP_ZERO_BLOCKS)

// scratch (static device arrays; no cudaMalloc allowed)
__device__ __align__(1024) __half g_encHT[(size_t)M_TOTAL * H_DIM];
__device__ __align__(1024) __half g_VtHT[(size_t)C_DIM * H_DIM];
__device__ float g_dpp[4][B_DIM * C_DIM];
__device__ float g_scores[M_TOTAL];

#define SW128(o) ((o) ^ (((o) >> 3) & 0x70))

// ------------------------------- PTX helpers -------------------------------

__device__ __forceinline__ uint32_t smem_u32(const void* p) {
    uint32_t a;
    asm("{ .reg .u64 t; cvta.to.shared.u64 t, %1; cvt.u32.u64 %0, t; }" : "=r"(a) : "l"(p));
    return a;
}

__device__ __forceinline__ void bulk_cp(uint32_t dst, const void* src,
                                        uint32_t bytes, uint32_t mbar) {
    asm volatile(
        "cp.async.bulk.shared::cluster.global.mbarrier::complete_tx::bytes "
        "[%0], [%1], %2, [%3];"
        :: "r"(dst), "l"(src), "r"(bytes), "r"(mbar) : "memory");
}

__device__ __forceinline__ void mbar_init(uint32_t a, uint32_t cnt) {
    asm volatile("mbarrier.init.shared.b64 [%0], %1;" :: "r"(a), "r"(cnt) : "memory");
}

__device__ __forceinline__ void mbar_expect_tx(uint32_t a, uint32_t n) {
    asm volatile("mbarrier.arrive.expect_tx.shared.b64 _, [%0], %1;"
                 :: "r"(a), "r"(n) : "memory");
}

__device__ __forceinline__ void mbar_arrive(uint32_t a) {
    asm volatile("mbarrier.arrive.shared.b64 _, [%0];" :: "r"(a) : "memory");
}

__device__ __forceinline__ void mbar_wait(uint32_t a, uint32_t phase) {
    asm volatile(
        "{\n\t.reg .pred P;\n"
        "WL_%=:\n\t"
        "mbarrier.try_wait.parity.acquire.cta.shared::cta.b64 P, [%0], %1, 0x989680;\n\t"
        "@P bra WD_%=;\n\t"
        "bra WL_%=;\n"
        "WD_%=:\n\t}"
        :: "r"(a), "r"(phase) : "memory");
}

__device__ __forceinline__ void ldsm4(uint32_t& r0, uint32_t& r1, uint32_t& r2,
                                      uint32_t& r3, uint32_t addr) {
    asm volatile("ldmatrix.sync.aligned.m8n8.x4.shared.b16 {%0,%1,%2,%3}, [%4];"
                 : "=r"(r0), "=r"(r1), "=r"(r2), "=r"(r3) : "r"(addr));
}

__device__ __forceinline__ void mma16816(float* c, uint32_t a0, uint32_t a1,
                                         uint32_t a2, uint32_t a3,
                                         uint32_t b0, uint32_t b1) {
    asm volatile(
        "mma.sync.aligned.m16n8k16.row.col.f32.f16.f16.f32 "
        "{%0,%1,%2,%3}, {%4,%5,%6,%7}, {%8,%9}, {%0,%1,%2,%3};"
        : "+f"(c[0]), "+f"(c[1]), "+f"(c[2]), "+f"(c[3])
        : "r"(a0), "r"(a1), "r"(a2), "r"(a3), "r"(b0), "r"(b1));
}

__device__ __forceinline__ float tanh_ap(float x) {
    float y;
    asm("tanh.approx.f32 %0, %1;" : "=f"(y) : "f"(x));
    return y;
}

// ------------------------- prep: 4 fused sub-jobs --------------------------
// [0,16384): convert enc (2 chunks/thread, kt & kt+8)
// [16384,17408): transpose V
// [17408,17440): dp partials (W read once)
// [17440,17472): zero g_scores

__global__ __launch_bounds__(256) void prep_kernel(
    const float* __restrict__ enc, const float* __restrict__ V,
    const float* __restrict__ dec, const float* __restrict__ W) {
    __shared__ float sh[32 * 256];   // 32KB, aliased by sub-jobs
    const int bid = blockIdx.x;
    const int tid = threadIdx.x;

    if (bid < PREP_CONV_BLOCKS) {
        size_t i = (size_t)bid * 256 + tid;
        const int c16 = (int)(i & 7);
        const int row = (int)((i >> 3) & 127);
        const int ktl = (int)((i >> 10) & 7);
        const int mtile = (int)(i >> 13);
        const float* src = enc + ((size_t)mtile * 128 + row) * H_DIM + ktl * 64 + c16 * 8;
        char* dstb = (char*)g_encHT + (((size_t)mtile * 16 + ktl) << 14) +
                     SW128(row * 128 + c16 * 16);
#pragma unroll
        for (int d = 0; d < 2; d++) {
            const float4* s = (const float4*)(src + d * 512);
            float4 v0 = s[0], v1 = s[1];
            __half2 h0 = __floats2half2_rn(v0.x, v0.y);
            __half2 h1 = __floats2half2_rn(v0.z, v0.w);
            __half2 h2 = __floats2half2_rn(v1.x, v1.y);
            __half2 h3 = __floats2half2_rn(v1.z, v1.w);
            uint4 u;
            u.x = *(uint32_t*)&h0; u.y = *(uint32_t*)&h1;
            u.z = *(uint32_t*)&h2; u.w = *(uint32_t*)&h3;
            *(uint4*)(dstb + (size_t)d * 8 * 16384) = u;
        }
    } else if (bid < PREP_CONV_BLOCKS + PREP_TRANS_BLOCKS) {
        float (*t)[33] = (float(*)[33])sh;
        int tb = bid - PREP_CONV_BLOCKS;
        int bx = tb & 31, by = tb >> 5;
        int tx = tid & 31, ty = tid >> 5;   // 32 x 8
#pragma unroll
        for (int j = 0; j < 32; j += 8)
            t[ty + j][tx] = V[(size_t)(by * 32 + ty + j) * C_DIM + bx * 32 + tx];
        __syncthreads();
#pragma unroll
        for (int j = 0; j < 32; j += 8) {
            int n = bx * 32 + ty + j;
            int k = by * 32 + tx;
            int nc = n >> 7, row = n & 127;
            int kt = k >> 6, c16 = (k >> 3) & 7, r8 = k & 7;
            size_t off = (((size_t)nc * 16 + kt) << 14) +
                         SW128(row * 128 + c16 * 16) + r8 * 2;
            *(__half*)((char*)g_VtHT + off) = __float2half(t[tx][ty + j]);
        }
    } else if (bid < PREP_CONV_BLOCKS + PREP_TRANS_BLOCKS + PREP_DP_BLOCKS) {
        int db = bid - PREP_CONV_BLOCKS - PREP_TRANS_BLOCKS;
        int cb = db & 7, hc = db >> 3;
        for (int i = tid; i < 32 * 256; i += 256) {
            int b = i >> 8, h = i & 255;
            sh[i] = dec[b * H_DIM + hc * 256 + h];
        }
        __syncthreads();
        if (tid < 128) {
            int c = cb * 128 + tid;
            float acc[32];
#pragma unroll
            for (int b = 0; b < 32; b++) acc[b] = 0.f;
#pragma unroll 4
            for (int h = 0; h < 256; h++) {
                float wv = W[(size_t)(hc * 256 + h) * C_DIM + c];
#pragma unroll
                for (int b = 0; b < 32; b++) acc[b] += sh[b * 256 + h] * wv;
            }
#pragma unroll
            for (int b = 0; b < 32; b++) g_dpp[hc][b * C_DIM + c] = acc[b];
        }
    } else {
        int zb = bid - PREP_CONV_BLOCKS - PREP_TRANS_BLOCKS - PREP_DP_BLOCKS;
        float4 z = {0.f, 0.f, 0.f, 0.f};
        float4* dst = (float4*)g_scores + (size_t)zb * 512 + tid;
        dst[0] = z;
        dst[256] = z;
    }
}

// ---------------- context with fused softmax (fp16, 16B loads) -------------
// block = (kt, b): computes b's softmax stats from g_scores inline, builds
// align in smem, then the 16B-load weighted sum over the fp16 tiled enc.

__global__ __launch_bounds__(256) void context_kernel(float* __restrict__ out) {
    const int kt = blockIdx.x, b = blockIdx.y;
    const int tid = threadIdx.x;
    __shared__ float sal[T_DIM];            // 8KB
    __shared__ float red[64][33];           // 8.25KB, padded
    __shared__ float sr[256];

    // --- inline softmax over g_scores[b,:] ---
    float v[8];
    float m = -1e30f;
#pragma unroll
    for (int j = 0; j < 8; j++) {
        v[j] = g_scores[b * T_DIM + j * 256 + tid];
        m = fmaxf(m, v[j]);
    }
    sr[tid] = m;
    __syncthreads();
    for (int s = 128; s > 0; s >>= 1) {
        if (tid < s) sr[tid] = fmaxf(sr[tid], sr[tid + s]);
        __syncthreads();
    }
    m = sr[0];
    __syncthreads();
    float sum = 0.f;
#pragma unroll
    for (int j = 0; j < 8; j++) {
        v[j] = __expf(v[j] - m);
        sum += v[j];
    }
    sr[tid] = sum;
    __syncthreads();
    for (int s = 128; s > 0; s >>= 1) {
        if (tid < s) sr[tid] += sr[tid + s];
        __syncthreads();
    }
    float inv = 1.f / sr[0];
#pragma unroll
    for (int j = 0; j < 8; j++) sal[j * 256 + tid] = v[j] * inv;
    __syncthreads();

    // --- weighted sum over enc (fp16 tiled) ---
    const int c16 = tid & 7;
    const int rbase = tid >> 3;             // 0..31
    float acc[8];
#pragma unroll
    for (int j = 0; j < 8; j++) acc[j] = 0.f;

#pragma unroll 1
    for (int i = 0; i < 16; i++) {
        const char* tile = (const char*)g_encHT +
                           (((size_t)(b * 16 + i) * 16 + kt) << 14);
#pragma unroll
        for (int rg = 0; rg < 4; rg++) {
            int r = rbase + rg * 32;
            uint4 u = *(const uint4*)(tile + SW128((uint32_t)(r * 128 + c16 * 16)));
            float a = sal[i * 128 + r];
            float2 f0 = __half22float2(*(__half2*)&u.x);
            float2 f1 = __half22float2(*(__half2*)&u.y);
            float2 f2 = __half22float2(*(__half2*)&u.z);
            float2 f3 = __half22float2(*(__half2*)&u.w);
            acc[0] += a * f0.x; acc[1] += a * f0.y;
            acc[2] += a * f1.x; acc[3] += a * f1.y;
            acc[4] += a * f2.x; acc[5] += a * f2.y;
            acc[6] += a * f3.x; acc[7] += a * f3.y;
        }
    }
#pragma unroll
    for (int j = 0; j < 8; j++) red[c16 * 8 + j][rbase] = acc[j];
    __syncthreads();
    if (tid < 64) {
        float s = 0.f;
#pragma unroll
        for (int i = 0; i < 32; i++) s += red[tid][i];
        out[b * H_DIM + kt * 64 + tid] = s;
    }
}

// ------------------------------- GEMM kernel -------------------------------
// R13/R10 GEMM; ONLY change: kt==0 sdp load folds the dp reduction
// (bias + 4 partials). Persistent 296 CTAs, 3-stage bulk-copy ring,
// empty-mbarrier ring, sdp/sw double-buffered, atomicAdd score partials.

__global__ void __launch_bounds__(GEMM_THREADS)
gemm_scores_kernel(const float* __restrict__ w_vec,
                   const float* __restrict__ bias) {
    extern __shared__ __align__(1024) char smem[];
    uint32_t sb = smem_u32(smem);
    const int tid = threadIdx.x;
    const int lane = tid & 31;
    const int wid = tid >> 5;
    const int warp_m = wid & 1;
    const int warp_n = wid >> 1;
    const int bid = blockIdx.x;

    float* sdp = (float*)(smem + OFF_DP);   // [2][128]
    float* sw = (float*)(smem + OFF_W);     // [2][128]
    float* sred = (float*)(smem + OFF_RED);

    const uint32_t mb_full = sb + OFF_MBAR;
    const uint32_t mb_empty = sb + OFF_MBAR + 32;

    uint32_t a_off[4];
#pragma unroll
    for (int mi = 0; mi < 4; mi++) {
        int ar = warp_m * 64 + mi * 16 + (lane & 15);
        a_off[mi] = SW128(ar * 128 + (lane >> 4) * 16);
    }
    const int b_row_in = (lane & 7) + ((lane >> 4) & 1) * 8;
    const uint32_t b_koff = ((lane >> 3) & 1) * 16;
    uint32_t b_off[4];
#pragma unroll
    for (int bg = 0; bg < 4; bg++) {
        int brow = warp_n * 64 + bg * 16 + b_row_in;
        b_off[bg] = SW128(brow * 128 + b_koff);
    }

    const char* encT = (const char*)g_encHT;
    const char* vtT = (const char*)g_VtHT;

    const int n_units = (NUM_UNITS - bid + GEMM_CTAS - 1) / GEMM_CTAS;
    const int total_stages = n_units * 32;

    if (tid == 0) {
#pragma unroll
        for (int b = 0; b < NSTAGES; b++) {
            mbar_init(mb_full + b * 8, 1);
            mbar_init(mb_empty + b * 8, 4);   // one arrive per warp
        }
    }
    __syncthreads();

#define STAGE_SRC(s, asrc, bsrc)                                          \
    {                                                                     \
        int u_ = bid + ((s) >> 5) * GEMM_CTAS;                            \
        int mtile_ = u_ >> 2;                                             \
        int loc_ = (s) & 31;                                              \
        int nc_ = (u_ & 3) * 2 + (loc_ >> 4);                             \
        int kt_ = loc_ & 15;                                              \
        asrc = encT + (((size_t)mtile_ * 16 + kt_) << 14);                \
        bsrc = vtT + (((size_t)nc_ * 16 + kt_) << 14);                    \
    }

    if (tid == 0) {
#pragma unroll
        for (int s = 0; s < NSTAGES - 1; s++) {
            const char *as_, *bs_;
            STAGE_SRC(s, as_, bs_);
            uint32_t mb = mb_full + s * 8;
            uint32_t dst = sb + s * STAGE_BYTES;
            mbar_expect_tx(mb, STAGE_BYTES);
            bulk_cp(dst, as_, 16384, mb);
            bulk_cp(dst + 16384, bs_, 16384, mb);
        }
    }

    float acc[4][8][4];
#pragma unroll
    for (int mi = 0; mi < 4; mi++)
#pragma unroll
        for (int ni = 0; ni < 8; ni++)
#pragma unroll
            for (int r = 0; r < 4; r++) acc[mi][ni][r] = 0.f;
    float p[8];
#pragma unroll
    for (int j = 0; j < 8; j++) p[j] = 0.f;

    uint32_t eph0 = 0, eph1 = 0, eph2 = 0;   // producer empty-phases

#pragma unroll 1
    for (int s = 0; s < total_stages; s++) {
        const int u = bid + (s >> 5) * GEMM_CTAS;
        const int mtile = u >> 2;
        const int loc = s & 31;
        const int nc = (u & 3) * 2 + (loc >> 4);
        const int kt = loc & 15;
        const int h = loc >> 4;            // sdp/sw buffer index
        const int bidx = mtile >> 4;

        if (tid == 0 && s + NSTAGES - 1 < total_stages) {
            const int sp = s + NSTAGES - 1;
            const int bb = sp % NSTAGES;
            if (sp >= NSTAGES) {           // buffer previously consumed
                if (bb == 0)      { mbar_wait(mb_empty + 0,  eph0); eph0 ^= 1; }
                else if (bb == 1) { mbar_wait(mb_empty + 8,  eph1); eph1 ^= 1; }
                else              { mbar_wait(mb_empty + 16, eph2); eph2 ^= 1; }
            }
            const char *as_, *bs_;
            STAGE_SRC(sp, as_, bs_);
            uint32_t mb = mb_full + bb * 8;
            uint32_t dst = sb + bb * STAGE_BYTES;
            mbar_expect_tx(mb, STAGE_BYTES);
            bulk_cp(dst, as_, 16384, mb);
            bulk_cp(dst + 16384, bs_, 16384, mb);
        }
        if (kt == 0) {
            int idx = bidx * C_DIM + nc * N_CHUNK + tid;
            sdp[h * 128 + tid] = bias[nc * N_CHUNK + tid] + g_dpp[0][idx] +
                                 g_dpp[1][idx] + g_dpp[2][idx] + g_dpp[3][idx];
            sw[h * 128 + tid] = w_vec[nc * N_CHUNK + tid];
        }
        mbar_wait(mb_full + (s % NSTAGES) * 8, (s / NSTAGES) & 1);

        uint32_t stA = sb + (s % NSTAGES) * STAGE_BYTES;
        uint32_t stB = stA + 16384;
#pragma unroll
        for (int ks = 0; ks < 4; ks++) {
            const uint32_t kx = (uint32_t)(ks * 32);
            uint32_t af[4][4];
#pragma unroll
            for (int mi = 0; mi < 4; mi++)
                ldsm4(af[mi][0], af[mi][1], af[mi][2], af[mi][3],
                      stA + (a_off[mi] ^ kx));
            uint32_t bf[4][4];
#pragma unroll
            for (int bg = 0; bg < 4; bg++)
                ldsm4(bf[bg][0], bf[bg][1], bf[bg][2], bf[bg][3],
                      stB + (b_off[bg] ^ kx));
            if (ks == 3 && lane == 0)      // last smem read of this stage done
                mbar_arrive(mb_empty + (s % NSTAGES) * 8);
#pragma unroll
            for (int mi = 0; mi < 4; mi++)
#pragma unroll
                for (int ni = 0; ni < 8; ni++) {
                    int bg = ni >> 1, sub = (ni & 1) * 2;
                    mma16816(acc[mi][ni], af[mi][0], af[mi][1], af[mi][2],
                             af[mi][3], bf[bg][sub], bf[bg][sub + 1]);
                }
        }

        if (kt == 15) {
#pragma unroll
            for (int mi = 0; mi < 4; mi++)
#pragma unroll
                for (int ni = 0; ni < 8; ni++) {
                    int col = warp_n * 64 + ni * 8 + (lane & 3) * 2;
                    float d0 = sdp[h * 128 + col], d1 = sdp[h * 128 + col + 1];
                    float w0 = sw[h * 128 + col], w1 = sw[h * 128 + col + 1];
                    float* c = acc[mi][ni];
                    p[mi * 2 + 0] += tanh_ap(c[0] + d0) * w0 + tanh_ap(c[1] + d1) * w1;
                    p[mi * 2 + 1] += tanh_ap(c[2] + d0) * w0 + tanh_ap(c[3] + d1) * w1;
                    c[0] = 0.f; c[1] = 0.f; c[2] = 0.f; c[3] = 0.f;
                }
        }
        if (loc == 31) {
#pragma unroll
            for (int j = 0; j < 8; j++) {
                p[j] += __shfl_xor_sync(0xFFFFFFFF, p[j], 1);
                p[j] += __shfl_xor_sync(0xFFFFFFFF, p[j], 2);
            }
            if (warp_n == 0 && (lane & 3) == 0) {
#pragma unroll
                for (int j = 0; j < 8; j++) {
                    int row = warp_m * 64 + (j >> 1) * 16 + (j & 1) * 8 + (lane >> 2);
                    sred[row] = p[j];
                }
            }
            __syncthreads();
            if (warp_n == 1 && (lane & 3) == 0) {
#pragma unroll
                for (int j = 0; j < 8; j++) {
                    int row = warp_m * 64 + (j >> 1) * 16 + (j & 1) * 8 + (lane >> 2);
                    sred[row] += p[j];
                }
            }
            __syncthreads();
            atomicAdd(&g_scores[mtile * CTA_M + tid], sred[tid]);
#pragma unroll
            for (int j = 0; j < 8; j++) p[j] = 0.f;
        }
    }
#undef STAGE_SRC
}

// -------------------------------- launcher ---------------------------------

extern "C" void kernel_launch(void* const* d_in, const int* in_sizes, int n_in,
                              void* d_out, int out_size) {
    const float* dec  = (const float*)d_in[0];
    const float* enc  = (const float*)d_in[1];
    const float* W    = (const float*)d_in[2];
    const float* V    = (const float*)d_in[3];
    const float* bias = (const float*)d_in[4];
    const float* w    = (const float*)d_in[5];
    float* out = (float*)d_out;

    cudaFuncSetAttribute(gemm_scores_kernel,
                         cudaFuncAttributeMaxDynamicSharedMemorySize, SMEM_TOTAL);

    prep_kernel<<<PREP_BLOCKS, 256>>>(enc, V, dec, W);               // 1
    gemm_scores_kernel<<<GEMM_CTAS, GEMM_THREADS, SMEM_TOTAL>>>(w, bias);  // 2
    context_kernel<<<dim3(16, 32), 256>>>(out);                      // 3
}

// round 15
// speedup vs baseline: 1.2150x; 1.2150x over previous
#include <cuda_runtime.h>
#include <cuda_fp16.h>
#include <cstdint>

// ---------------------------------------------------------------------------
// Bahdanau additive attention, B=32, T=2048, H=C=1024.
// R15 = R14 minus the fusion mistake. R14's fused prep hit regs=140 (dp's
// acc[32] taxed ALL 16K convert blocks) -> 1 CTA/SM -> convert at 1.9TB/s,
// 204us. Fix: dp_part back to its own kernel; prep = convert + transpose +
// zero-scores (low-reg, 4.2KB smem). KEEP the two free R14 fusions:
// GEMM folds the dp reduction (bias + 4 partials at kt==0) and softmax is
// fused into context. 4 launches.
// RULE LEARNED: never fuse high-register and BW-bound sub-jobs in one kernel.
// ---------------------------------------------------------------------------

#define B_DIM 32
#define T_DIM 2048
#define H_DIM 1024
#define C_DIM 1024
#define M_TOTAL (B_DIM * T_DIM)      // 65536

#define CTA_M 128
#define N_CHUNK 128
#define NUM_NC (C_DIM / N_CHUNK)     // 8
#define K_STAGE 64
#define NUM_KT (H_DIM / K_STAGE)     // 16
#define NUM_MTILES (M_TOTAL / CTA_M) // 512
#define NUM_UNITS (NUM_MTILES * 4)   // 2048 (mtile x nc-pair)
#define GEMM_CTAS 296                // 2 per SM x 148
#define GEMM_THREADS 128             // 4 warps: 2(M) x 2(N), warp tile 64x64

#define STAGE_BYTES 32768            // A 16KB + B 16KB
#define NSTAGES 3
#define OFF_MBAR (NSTAGES * STAGE_BYTES)   // full[3] at +0, empty[3] at +32
#define OFF_DP (OFF_MBAR + 64)             // 2 x 128 f (double-buffered)
#define OFF_W (OFF_DP + 1024)              // 2 x 128 f
#define OFF_RED (OFF_W + 1024)             // 128 f
#define SMEM_TOTAL (OFF_RED + 512)         // 100928 (x2 CTA/SM = 201856 <= 227KB)

// prep block ranges (NO dp here — register-pressure poison, see header)
#define PREP_CONV_BLOCKS 16384
#define PREP_TRANS_BLOCKS 1024
#define PREP_ZERO_BLOCKS 32
#define PREP_BLOCKS (PREP_CONV_BLOCKS + PREP_TRANS_BLOCKS + PREP_ZERO_BLOCKS)

// scratch (static device arrays; no cudaMalloc allowed)
__device__ __align__(1024) __half g_encHT[(size_t)M_TOTAL * H_DIM];
__device__ __align__(1024) __half g_VtHT[(size_t)C_DIM * H_DIM];
__device__ float g_dpp[4][B_DIM * C_DIM];
__device__ float g_scores[M_TOTAL];

#define SW128(o) ((o) ^ (((o) >> 3) & 0x70))

// ------------------------------- PTX helpers -------------------------------

__device__ __forceinline__ uint32_t smem_u32(const void* p) {
    uint32_t a;
    asm("{ .reg .u64 t; cvta.to.shared.u64 t, %1; cvt.u32.u64 %0, t; }" : "=r"(a) : "l"(p));
    return a;
}

__device__ __forceinline__ void bulk_cp(uint32_t dst, const void* src,
                                        uint32_t bytes, uint32_t mbar) {
    asm volatile(
        "cp.async.bulk.shared::cluster.global.mbarrier::complete_tx::bytes "
        "[%0], [%1], %2, [%3];"
        :: "r"(dst), "l"(src), "r"(bytes), "r"(mbar) : "memory");
}

__device__ __forceinline__ void mbar_init(uint32_t a, uint32_t cnt) {
    asm volatile("mbarrier.init.shared.b64 [%0], %1;" :: "r"(a), "r"(cnt) : "memory");
}

__device__ __forceinline__ void mbar_expect_tx(uint32_t a, uint32_t n) {
    asm volatile("mbarrier.arrive.expect_tx.shared.b64 _, [%0], %1;"
                 :: "r"(a), "r"(n) : "memory");
}

__device__ __forceinline__ void mbar_arrive(uint32_t a) {
    asm volatile("mbarrier.arrive.shared.b64 _, [%0];" :: "r"(a) : "memory");
}

__device__ __forceinline__ void mbar_wait(uint32_t a, uint32_t phase) {
    asm volatile(
        "{\n\t.reg .pred P;\n"
        "WL_%=:\n\t"
        "mbarrier.try_wait.parity.acquire.cta.shared::cta.b64 P, [%0], %1, 0x989680;\n\t"
        "@P bra WD_%=;\n\t"
        "bra WL_%=;\n"
        "WD_%=:\n\t}"
        :: "r"(a), "r"(phase) : "memory");
}

__device__ __forceinline__ void ldsm4(uint32_t& r0, uint32_t& r1, uint32_t& r2,
                                      uint32_t& r3, uint32_t addr) {
    asm volatile("ldmatrix.sync.aligned.m8n8.x4.shared.b16 {%0,%1,%2,%3}, [%4];"
                 : "=r"(r0), "=r"(r1), "=r"(r2), "=r"(r3) : "r"(addr));
}

__device__ __forceinline__ void mma16816(float* c, uint32_t a0, uint32_t a1,
                                         uint32_t a2, uint32_t a3,
                                         uint32_t b0, uint32_t b1) {
    asm volatile(
        "mma.sync.aligned.m16n8k16.row.col.f32.f16.f16.f32 "
        "{%0,%1,%2,%3}, {%4,%5,%6,%7}, {%8,%9}, {%0,%1,%2,%3};"
        : "+f"(c[0]), "+f"(c[1]), "+f"(c[2]), "+f"(c[3])
        : "r"(a0), "r"(a1), "r"(a2), "r"(a3), "r"(b0), "r"(b1));
}

__device__ __forceinline__ float tanh_ap(float x) {
    float y;
    asm("tanh.approx.f32 %0, %1;" : "=f"(y) : "f"(x));
    return y;
}

// ------------------- prep: convert + transpose + zero ----------------------
// [0,16384): convert enc (2 chunks/thread, kt & kt+8)   — low regs, no smem
// [16384,17408): transpose V                            — 4.2KB smem
// [17408,17440): zero g_scores

__global__ __launch_bounds__(256) void prep_kernel(
    const float* __restrict__ enc, const float* __restrict__ V) {
    __shared__ float t[32][33];
    const int bid = blockIdx.x;
    const int tid = threadIdx.x;

    if (bid < PREP_CONV_BLOCKS) {
        size_t i = (size_t)bid * 256 + tid;
        const int c16 = (int)(i & 7);
        const int row = (int)((i >> 3) & 127);
        const int ktl = (int)((i >> 10) & 7);
        const int mtile = (int)(i >> 13);
        const float* src = enc + ((size_t)mtile * 128 + row) * H_DIM + ktl * 64 + c16 * 8;
        char* dstb = (char*)g_encHT + (((size_t)mtile * 16 + ktl) << 14) +
                     SW128(row * 128 + c16 * 16);
#pragma unroll
        for (int d = 0; d < 2; d++) {
            const float4* s = (const float4*)(src + d * 512);
            float4 v0 = s[0], v1 = s[1];
            __half2 h0 = __floats2half2_rn(v0.x, v0.y);
            __half2 h1 = __floats2half2_rn(v0.z, v0.w);
            __half2 h2 = __floats2half2_rn(v1.x, v1.y);
            __half2 h3 = __floats2half2_rn(v1.z, v1.w);
            uint4 u;
            u.x = *(uint32_t*)&h0; u.y = *(uint32_t*)&h1;
            u.z = *(uint32_t*)&h2; u.w = *(uint32_t*)&h3;
            *(uint4*)(dstb + (size_t)d * 8 * 16384) = u;
        }
    } else if (bid < PREP_CONV_BLOCKS + PREP_TRANS_BLOCKS) {
        int tb = bid - PREP_CONV_BLOCKS;
        int bx = tb & 31, by = tb >> 5;
        int tx = tid & 31, ty = tid >> 5;   // 32 x 8
#pragma unroll
        for (int j = 0; j < 32; j += 8)
            t[ty + j][tx] = V[(size_t)(by * 32 + ty + j) * C_DIM + bx * 32 + tx];
        __syncthreads();
#pragma unroll
        for (int j = 0; j < 32; j += 8) {
            int n = bx * 32 + ty + j;
            int k = by * 32 + tx;
            int nc = n >> 7, row = n & 127;
            int kt = k >> 6, c16 = (k >> 3) & 7, r8 = k & 7;
            size_t off = (((size_t)nc * 16 + kt) << 14) +
                         SW128(row * 128 + c16 * 16) + r8 * 2;
            *(__half*)((char*)g_VtHT + off) = __float2half(t[tx][ty + j]);
        }
    } else {
        int zb = bid - PREP_CONV_BLOCKS - PREP_TRANS_BLOCKS;
        float4 z = {0.f, 0.f, 0.f, 0.f};
        float4* dst = (float4*)g_scores + (size_t)zb * 512 + tid;
        dst[0] = z;
        dst[256] = z;
    }
}

// -------------------- dp partials (separate: high-reg job) -----------------

__global__ void dp_part_kernel(const float* __restrict__ dec,
                               const float* __restrict__ W) {
    __shared__ float sdec[32 * 256];
    int cb = blockIdx.x, hc = blockIdx.y;
    int tid = threadIdx.x;
    for (int i = tid; i < 32 * 256; i += 128) {
        int b = i >> 8, h = i & 255;
        sdec[i] = dec[b * H_DIM + hc * 256 + h];
    }
    __syncthreads();
    int c = cb * 128 + tid;
    float acc[32];
#pragma unroll
    for (int b = 0; b < 32; b++) acc[b] = 0.f;
#pragma unroll 4
    for (int h = 0; h < 256; h++) {
        float wv = W[(size_t)(hc * 256 + h) * C_DIM + c];
#pragma unroll
        for (int b = 0; b < 32; b++) acc[b] += sdec[b * 256 + h] * wv;
    }
#pragma unroll
    for (int b = 0; b < 32; b++) g_dpp[hc][b * C_DIM + c] = acc[b];
}

// ---------------- context with fused softmax (fp16, 16B loads) -------------

__global__ __launch_bounds__(256) void context_kernel(float* __restrict__ out) {
    const int kt = blockIdx.x, b = blockIdx.y;
    const int tid = threadIdx.x;
    __shared__ float sal[T_DIM];            // 8KB
    __shared__ float red[64][33];           // 8.25KB, padded
    __shared__ float sr[256];

    // --- inline softmax over g_scores[b,:] ---
    float v[8];
    float m = -1e30f;
#pragma unroll
    for (int j = 0; j < 8; j++) {
        v[j] = g_scores[b * T_DIM + j * 256 + tid];
        m = fmaxf(m, v[j]);
    }
    sr[tid] = m;
    __syncthreads();
    for (int s = 128; s > 0; s >>= 1) {
        if (tid < s) sr[tid] = fmaxf(sr[tid], sr[tid + s]);
        __syncthreads();
    }
    m = sr[0];
    __syncthreads();
    float sum = 0.f;
#pragma unroll
    for (int j = 0; j < 8; j++) {
        v[j] = __expf(v[j] - m);
        sum += v[j];
    }
    sr[tid] = sum;
    __syncthreads();
    for (int s = 128; s > 0; s >>= 1) {
        if (tid < s) sr[tid] += sr[tid + s];
        __syncthreads();
    }
    float inv = 1.f / sr[0];
#pragma unroll
    for (int j = 0; j < 8; j++) sal[j * 256 + tid] = v[j] * inv;
    __syncthreads();

    // --- weighted sum over enc (fp16 tiled) ---
    const int c16 = tid & 7;
    const int rbase = tid >> 3;             // 0..31
    float acc[8];
#pragma unroll
    for (int j = 0; j < 8; j++) acc[j] = 0.f;

#pragma unroll 1
    for (int i = 0; i < 16; i++) {
        const char* tile = (const char*)g_encHT +
                           (((size_t)(b * 16 + i) * 16 + kt) << 14);
#pragma unroll
        for (int rg = 0; rg < 4; rg++) {
            int r = rbase + rg * 32;
            uint4 u = *(const uint4*)(tile + SW128((uint32_t)(r * 128 + c16 * 16)));
            float a = sal[i * 128 + r];
            float2 f0 = __half22float2(*(__half2*)&u.x);
            float2 f1 = __half22float2(*(__half2*)&u.y);
            float2 f2 = __half22float2(*(__half2*)&u.z);
            float2 f3 = __half22float2(*(__half2*)&u.w);
            acc[0] += a * f0.x; acc[1] += a * f0.y;
            acc[2] += a * f1.x; acc[3] += a * f1.y;
            acc[4] += a * f2.x; acc[5] += a * f2.y;
            acc[6] += a * f3.x; acc[7] += a * f3.y;
        }
    }
#pragma unroll
    for (int j = 0; j < 8; j++) red[c16 * 8 + j][rbase] = acc[j];
    __syncthreads();
    if (tid < 64) {
        float s = 0.f;
#pragma unroll
        for (int i = 0; i < 32; i++) s += red[tid][i];
        out[b * H_DIM + kt * 64 + tid] = s;
    }
}

// ------------------------------- GEMM kernel -------------------------------
// R13/R10 GEMM; kt==0 sdp load folds the dp reduction (bias + 4 partials).
// Persistent 296 CTAs, 3-stage bulk-copy ring, empty-mbarrier ring, sdp/sw
// double-buffered, atomicAdd score partials.

__global__ void __launch_bounds__(GEMM_THREADS)
gemm_scores_kernel(const float* __restrict__ w_vec,
                   const float* __restrict__ bias) {
    extern __shared__ __align__(1024) char smem[];
    uint32_t sb = smem_u32(smem);
    const int tid = threadIdx.x;
    const int lane = tid & 31;
    const int wid = tid >> 5;
    const int warp_m = wid & 1;
    const int warp_n = wid >> 1;
    const int bid = blockIdx.x;

    float* sdp = (float*)(smem + OFF_DP);   // [2][128]
    float* sw = (float*)(smem + OFF_W);     // [2][128]
    float* sred = (float*)(smem + OFF_RED);

    const uint32_t mb_full = sb + OFF_MBAR;
    const uint32_t mb_empty = sb + OFF_MBAR + 32;

    uint32_t a_off[4];
#pragma unroll
    for (int mi = 0; mi < 4; mi++) {
        int ar = warp_m * 64 + mi * 16 + (lane & 15);
        a_off[mi] = SW128(ar * 128 + (lane >> 4) * 16);
    }
    const int b_row_in = (lane & 7) + ((lane >> 4) & 1) * 8;
    const uint32_t b_koff = ((lane >> 3) & 1) * 16;
    uint32_t b_off[4];
#pragma unroll
    for (int bg = 0; bg < 4; bg++) {
        int brow = warp_n * 64 + bg * 16 + b_row_in;
        b_off[bg] = SW128(brow * 128 + b_koff);
    }

    const char* encT = (const char*)g_encHT;
    const char* vtT = (const char*)g_VtHT;

    const int n_units = (NUM_UNITS - bid + GEMM_CTAS - 1) / GEMM_CTAS;
    const int total_stages = n_units * 32;

    if (tid == 0) {
#pragma unroll
        for (int b = 0; b < NSTAGES; b++) {
            mbar_init(mb_full + b * 8, 1);
            mbar_init(mb_empty + b * 8, 4);   // one arrive per warp
        }
    }
    __syncthreads();

#define STAGE_SRC(s, asrc, bsrc)                                          \
    {                                                                     \
        int u_ = bid + ((s) >> 5) * GEMM_CTAS;                            \
        int mtile_ = u_ >> 2;                                             \
        int loc_ = (s) & 31;                                              \
        int nc_ = (u_ & 3) * 2 + (loc_ >> 4);                             \
        int kt_ = loc_ & 15;                                              \
        asrc = encT + (((size_t)mtile_ * 16 + kt_) << 14);                \
        bsrc = vtT + (((size_t)nc_ * 16 + kt_) << 14);                    \
    }

    if (tid == 0) {
#pragma unroll
        for (int s = 0; s < NSTAGES - 1; s++) {
            const char *as_, *bs_;
            STAGE_SRC(s, as_, bs_);
            uint32_t mb = mb_full + s * 8;
            uint32_t dst = sb + s * STAGE_BYTES;
            mbar_expect_tx(mb, STAGE_BYTES);
            bulk_cp(dst, as_, 16384, mb);
            bulk_cp(dst + 16384, bs_, 16384, mb);
        }
    }

    float acc[4][8][4];
#pragma unroll
    for (int mi = 0; mi < 4; mi++)
#pragma unroll
        for (int ni = 0; ni < 8; ni++)
#pragma unroll
            for (int r = 0; r < 4; r++) acc[mi][ni][r] = 0.f;
    float p[8];
#pragma unroll
    for (int j = 0; j < 8; j++) p[j] = 0.f;

    uint32_t eph0 = 0, eph1 = 0, eph2 = 0;   // producer empty-phases

#pragma unroll 1
    for (int s = 0; s < total_stages; s++) {
        const int u = bid + (s >> 5) * GEMM_CTAS;
        const int mtile = u >> 2;
        const int loc = s & 31;
        const int nc = (u & 3) * 2 + (loc >> 4);
        const int kt = loc & 15;
        const int h = loc >> 4;            // sdp/sw buffer index
        const int bidx = mtile >> 4;

        if (tid == 0 && s + NSTAGES - 1 < total_stages) {
            const int sp = s + NSTAGES - 1;
            const int bb = sp % NSTAGES;
            if (sp >= NSTAGES) {           // buffer previously consumed
                if (bb == 0)      { mbar_wait(mb_empty + 0,  eph0); eph0 ^= 1; }
                else if (bb == 1) { mbar_wait(mb_empty + 8,  eph1); eph1 ^= 1; }
                else              { mbar_wait(mb_empty + 16, eph2); eph2 ^= 1; }
            }
            const char *as_, *bs_;
            STAGE_SRC(sp, as_, bs_);
            uint32_t mb = mb_full + bb * 8;
            uint32_t dst = sb + bb * STAGE_BYTES;
            mbar_expect_tx(mb, STAGE_BYTES);
            bulk_cp(dst, as_, 16384, mb);
            bulk_cp(dst + 16384, bs_, 16384, mb);
        }
        if (kt == 0) {
            int idx = bidx * C_DIM + nc * N_CHUNK + tid;
            sdp[h * 128 + tid] = bias[nc * N_CHUNK + tid] + g_dpp[0][idx] +
                                 g_dpp[1][idx] + g_dpp[2][idx] + g_dpp[3][idx];
            sw[h * 128 + tid] = w_vec[nc * N_CHUNK + tid];
        }
        mbar_wait(mb_full + (s % NSTAGES) * 8, (s / NSTAGES) & 1);

        uint32_t stA = sb + (s % NSTAGES) * STAGE_BYTES;
        uint32_t stB = stA + 16384;
#pragma unroll
        for (int ks = 0; ks < 4; ks++) {
            const uint32_t kx = (uint32_t)(ks * 32);
            uint32_t af[4][4];
#pragma unroll
            for (int mi = 0; mi < 4; mi++)
                ldsm4(af[mi][0], af[mi][1], af[mi][2], af[mi][3],
                      stA + (a_off[mi] ^ kx));
            uint32_t bf[4][4];
#pragma unroll
            for (int bg = 0; bg < 4; bg++)
                ldsm4(bf[bg][0], bf[bg][1], bf[bg][2], bf[bg][3],
                      stB + (b_off[bg] ^ kx));
            if (ks == 3 && lane == 0)      // last smem read of this stage done
                mbar_arrive(mb_empty + (s % NSTAGES) * 8);
#pragma unroll
            for (int mi = 0; mi < 4; mi++)
#pragma unroll
                for (int ni = 0; ni < 8; ni++) {
                    int bg = ni >> 1, sub = (ni & 1) * 2;
                    mma16816(acc[mi][ni], af[mi][0], af[mi][1], af[mi][2],
                             af[mi][3], bf[bg][sub], bf[bg][sub + 1]);
                }
        }

        if (kt == 15) {
#pragma unroll
            for (int mi = 0; mi < 4; mi++)
#pragma unroll
                for (int ni = 0; ni < 8; ni++) {
                    int col = warp_n * 64 + ni * 8 + (lane & 3) * 2;
                    float d0 = sdp[h * 128 + col], d1 = sdp[h * 128 + col + 1];
                    float w0 = sw[h * 128 + col], w1 = sw[h * 128 + col + 1];
                    float* c = acc[mi][ni];
                    p[mi * 2 + 0] += tanh_ap(c[0] + d0) * w0 + tanh_ap(c[1] + d1) * w1;
                    p[mi * 2 + 1] += tanh_ap(c[2] + d0) * w0 + tanh_ap(c[3] + d1) * w1;
                    c[0] = 0.f; c[1] = 0.f; c[2] = 0.f; c[3] = 0.f;
                }
        }
        if (loc == 31) {
#pragma unroll
            for (int j = 0; j < 8; j++) {
                p[j] += __shfl_xor_sync(0xFFFFFFFF, p[j], 1);
                p[j] += __shfl_xor_sync(0xFFFFFFFF, p[j], 2);
            }
            if (warp_n == 0 && (lane & 3) == 0) {
#pragma unroll
                for (int j = 0; j < 8; j++) {
                    int row = warp_m * 64 + (j >> 1) * 16 + (j & 1) * 8 + (lane >> 2);
                    sred[row] = p[j];
                }
            }
            __syncthreads();
            if (warp_n == 1 && (lane & 3) == 0) {
#pragma unroll
                for (int j = 0; j < 8; j++) {
                    int row = warp_m * 64 + (j >> 1) * 16 + (j & 1) * 8 + (lane >> 2);
                    sred[row] += p[j];
                }
            }
            __syncthreads();
            atomicAdd(&g_scores[mtile * CTA_M + tid], sred[tid]);
#pragma unroll
            for (int j = 0; j < 8; j++) p[j] = 0.f;
        }
    }
#undef STAGE_SRC
}

// -------------------------------- launcher ---------------------------------

extern "C" void kernel_launch(void* const* d_in, const int* in_sizes, int n_in,
                              void* d_out, int out_size) {
    const float* dec  = (const float*)d_in[0];
    const float* enc  = (const float*)d_in[1];
    const float* W    = (const float*)d_in[2];
    const float* V    = (const float*)d_in[3];
    const float* bias = (const float*)d_in[4];
    const float* w    = (const float*)d_in[5];
    float* out = (float*)d_out;

    cudaFuncSetAttribute(gemm_scores_kernel,
                         cudaFuncAttributeMaxDynamicSharedMemorySize, SMEM_TOTAL);

    prep_kernel<<<PREP_BLOCKS, 256>>>(enc, V);                        // 1
    dp_part_kernel<<<dim3(8, 4), 128>>>(dec, W);                      // 2
    gemm_scores_kernel<<<GEMM_CTAS, GEMM_THREADS, SMEM_TOTAL>>>(w, bias);  // 3
    context_kernel<<<dim3(16, 32), 256>>>(out);                       // 4
}

// round 16
// speedup vs baseline: 1.2563x; 1.0340x over previous
#include <cuda_runtime.h>
#include <cuda_fp16.h>
#include <cstdint>

// ---------------------------------------------------------------------------
// Bahdanau additive attention, B=32, T=2048, H=C=1024.
// R16 (base = R15, 438.7us): ONE change — context split over blockIdx.z=2
// (grid 16x32x2 = 1024 blocks; R15 ncu showed 512 blocks -> 3.46 CTA/SM ->
// occ 42% -> 3.5TB/s). Each half sums 8 of 16 t-subtiles, atomicAdd to out;
// prep zero-range extended to cover out (poisoned each replay).
// ---------------------------------------------------------------------------

#define B_DIM 32
#define T_DIM 2048
#define H_DIM 1024
#define C_DIM 1024
#define M_TOTAL (B_DIM * T_DIM)      // 65536

#define CTA_M 128
#define N_CHUNK 128
#define NUM_NC (C_DIM / N_CHUNK)     // 8
#define K_STAGE 64
#define NUM_KT (H_DIM / K_STAGE)     // 16
#define NUM_MTILES (M_TOTAL / CTA_M) // 512
#define NUM_UNITS (NUM_MTILES * 4)   // 2048 (mtile x nc-pair)
#define GEMM_CTAS 296                // 2 per SM x 148
#define GEMM_THREADS 128             // 4 warps: 2(M) x 2(N), warp tile 64x64

#define STAGE_BYTES 32768            // A 16KB + B 16KB
#define NSTAGES 3
#define OFF_MBAR (NSTAGES * STAGE_BYTES)   // full[3] at +0, empty[3] at +32
#define OFF_DP (OFF_MBAR + 64)             // 2 x 128 f (double-buffered)
#define OFF_W (OFF_DP + 1024)              // 2 x 128 f
#define OFF_RED (OFF_W + 1024)             // 128 f
#define SMEM_TOTAL (OFF_RED + 512)         // 100928 (x2 CTA/SM = 201856 <= 227KB)

// prep block ranges (dp kept separate: register-pressure poison, see R14)
#define PREP_CONV_BLOCKS 16384
#define PREP_TRANS_BLOCKS 1024
#define PREP_ZERO_BLOCKS 48          // 32 zero g_scores (256KB), 16 zero out (128KB)
#define PREP_BLOCKS (PREP_CONV_BLOCKS + PREP_TRANS_BLOCKS + PREP_ZERO_BLOCKS)

// scratch (static device arrays; no cudaMalloc allowed)
__device__ __align__(1024) __half g_encHT[(size_t)M_TOTAL * H_DIM];
__device__ __align__(1024) __half g_VtHT[(size_t)C_DIM * H_DIM];
__device__ float g_dpp[4][B_DIM * C_DIM];
__device__ float g_scores[M_TOTAL];

#define SW128(o) ((o) ^ (((o) >> 3) & 0x70))

// ------------------------------- PTX helpers -------------------------------

__device__ __forceinline__ uint32_t smem_u32(const void* p) {
    uint32_t a;
    asm("{ .reg .u64 t; cvta.to.shared.u64 t, %1; cvt.u32.u64 %0, t; }" : "=r"(a) : "l"(p));
    return a;
}

__device__ __forceinline__ void bulk_cp(uint32_t dst, const void* src,
                                        uint32_t bytes, uint32_t mbar) {
    asm volatile(
        "cp.async.bulk.shared::cluster.global.mbarrier::complete_tx::bytes "
        "[%0], [%1], %2, [%3];"
        :: "r"(dst), "l"(src), "r"(bytes), "r"(mbar) : "memory");
}

__device__ __forceinline__ void mbar_init(uint32_t a, uint32_t cnt) {
    asm volatile("mbarrier.init.shared.b64 [%0], %1;" :: "r"(a), "r"(cnt) : "memory");
}

__device__ __forceinline__ void mbar_expect_tx(uint32_t a, uint32_t n) {
    asm volatile("mbarrier.arrive.expect_tx.shared.b64 _, [%0], %1;"
                 :: "r"(a), "r"(n) : "memory");
}

__device__ __forceinline__ void mbar_arrive(uint32_t a) {
    asm volatile("mbarrier.arrive.shared.b64 _, [%0];" :: "r"(a) : "memory");
}

__device__ __forceinline__ void mbar_wait(uint32_t a, uint32_t phase) {
    asm volatile(
        "{\n\t.reg .pred P;\n"
        "WL_%=:\n\t"
        "mbarrier.try_wait.parity.acquire.cta.shared::cta.b64 P, [%0], %1, 0x989680;\n\t"
        "@P bra WD_%=;\n\t"
        "bra WL_%=;\n"
        "WD_%=:\n\t}"
        :: "r"(a), "r"(phase) : "memory");
}

__device__ __forceinline__ void ldsm4(uint32_t& r0, uint32_t& r1, uint32_t& r2,
                                      uint32_t& r3, uint32_t addr) {
    asm volatile("ldmatrix.sync.aligned.m8n8.x4.shared.b16 {%0,%1,%2,%3}, [%4];"
                 : "=r"(r0), "=r"(r1), "=r"(r2), "=r"(r3) : "r"(addr));
}

__device__ __forceinline__ void mma16816(float* c, uint32_t a0, uint32_t a1,
                                         uint32_t a2, uint32_t a3,
                                         uint32_t b0, uint32_t b1) {
    asm volatile(
        "mma.sync.aligned.m16n8k16.row.col.f32.f16.f16.f32 "
        "{%0,%1,%2,%3}, {%4,%5,%6,%7}, {%8,%9}, {%0,%1,%2,%3};"
        : "+f"(c[0]), "+f"(c[1]), "+f"(c[2]), "+f"(c[3])
        : "r"(a0), "r"(a1), "r"(a2), "r"(a3), "r"(b0), "r"(b1));
}

__device__ __forceinline__ float tanh_ap(float x) {
    float y;
    asm("tanh.approx.f32 %0, %1;" : "=f"(y) : "f"(x));
    return y;
}

// ------------------- prep: convert + transpose + zero ----------------------
// [0,16384): convert enc (2 chunks/thread, kt & kt+8)
// [16384,17408): transpose V
// [17408,17440): zero g_scores; [17440,17456): zero out

__global__ __launch_bounds__(256) void prep_kernel(
    const float* __restrict__ enc, const float* __restrict__ V,
    float* __restrict__ out) {
    __shared__ float t[32][33];
    const int bid = blockIdx.x;
    const int tid = threadIdx.x;

    if (bid < PREP_CONV_BLOCKS) {
        size_t i = (size_t)bid * 256 + tid;
        const int c16 = (int)(i & 7);
        const int row = (int)((i >> 3) & 127);
        const int ktl = (int)((i >> 10) & 7);
        const int mtile = (int)(i >> 13);
        const float* src = enc + ((size_t)mtile * 128 + row) * H_DIM + ktl * 64 + c16 * 8;
        char* dstb = (char*)g_encHT + (((size_t)mtile * 16 + ktl) << 14) +
                     SW128(row * 128 + c16 * 16);
#pragma unroll
        for (int d = 0; d < 2; d++) {
            const float4* s = (const float4*)(src + d * 512);
            float4 v0 = s[0], v1 = s[1];
            __half2 h0 = __floats2half2_rn(v0.x, v0.y);
            __half2 h1 = __floats2half2_rn(v0.z, v0.w);
            __half2 h2 = __floats2half2_rn(v1.x, v1.y);
            __half2 h3 = __floats2half2_rn(v1.z, v1.w);
            uint4 u;
            u.x = *(uint32_t*)&h0; u.y = *(uint32_t*)&h1;
            u.z = *(uint32_t*)&h2; u.w = *(uint32_t*)&h3;
            *(uint4*)(dstb + (size_t)d * 8 * 16384) = u;
        }
    } else if (bid < PREP_CONV_BLOCKS + PREP_TRANS_BLOCKS) {
        int tb = bid - PREP_CONV_BLOCKS;
        int bx = tb & 31, by = tb >> 5;
        int tx = tid & 31, ty = tid >> 5;   // 32 x 8
#pragma unroll
        for (int j = 0; j < 32; j += 8)
            t[ty + j][tx] = V[(size_t)(by * 32 + ty + j) * C_DIM + bx * 32 + tx];
        __syncthreads();
#pragma unroll
        for (int j = 0; j < 32; j += 8) {
            int n = bx * 32 + ty + j;
            int k = by * 32 + tx;
            int nc = n >> 7, row = n & 127;
            int kt = k >> 6, c16 = (k >> 3) & 7, r8 = k & 7;
            size_t off = (((size_t)nc * 16 + kt) << 14) +
                         SW128(row * 128 + c16 * 16) + r8 * 2;
            *(__half*)((char*)g_VtHT + off) = __float2half(t[tx][ty + j]);
        }
    } else {
        int zb = bid - PREP_CONV_BLOCKS - PREP_TRANS_BLOCKS;
        float4 z = {0.f, 0.f, 0.f, 0.f};
        if (zb < 32) {
            float4* dst = (float4*)g_scores + (size_t)zb * 512 + tid;
            dst[0] = z;
            dst[256] = z;
        } else {
            float4* dst = (float4*)out + (size_t)(zb - 32) * 512 + tid;
            dst[0] = z;
            dst[256] = z;
        }
    }
}

// -------------------- dp partials (separate: high-reg job) -----------------

__global__ void dp_part_kernel(const float* __restrict__ dec,
                               const float* __restrict__ W) {
    __shared__ float sdec[32 * 256];
    int cb = blockIdx.x, hc = blockIdx.y;
    int tid = threadIdx.x;
    for (int i = tid; i < 32 * 256; i += 128) {
        int b = i >> 8, h = i & 255;
        sdec[i] = dec[b * H_DIM + hc * 256 + h];
    }
    __syncthreads();
    int c = cb * 128 + tid;
    float acc[32];
#pragma unroll
    for (int b = 0; b < 32; b++) acc[b] = 0.f;
#pragma unroll 4
    for (int h = 0; h < 256; h++) {
        float wv = W[(size_t)(hc * 256 + h) * C_DIM + c];
#pragma unroll
        for (int b = 0; b < 32; b++) acc[b] += sdec[b * 256 + h] * wv;
    }
#pragma unroll
    for (int b = 0; b < 32; b++) g_dpp[hc][b * C_DIM + c] = acc[b];
}

// ------------- context with fused softmax, z-split over t ------------------
// block = (kt, b, half): softmax stats inline (cheap), then the weighted sum
// over 8 of 16 t-subtiles; atomicAdd partial into out (zeroed by prep).

__global__ __launch_bounds__(256) void context_kernel(float* __restrict__ out) {
    const int kt = blockIdx.x, b = blockIdx.y;
    const int half = blockIdx.z;
    const int tid = threadIdx.x;
    __shared__ float sal[T_DIM];            // 8KB
    __shared__ float red[64][33];           // 8.25KB, padded
    __shared__ float sr[256];

    // --- inline softmax over g_scores[b,:] ---
    float v[8];
    float m = -1e30f;
#pragma unroll
    for (int j = 0; j < 8; j++) {
        v[j] = g_scores[b * T_DIM + j * 256 + tid];
        m = fmaxf(m, v[j]);
    }
    sr[tid] = m;
    __syncthreads();
    for (int s = 128; s > 0; s >>= 1) {
        if (tid < s) sr[tid] = fmaxf(sr[tid], sr[tid + s]);
        __syncthreads();
    }
    m = sr[0];
    __syncthreads();
    float sum = 0.f;
#pragma unroll
    for (int j = 0; j < 8; j++) {
        v[j] = __expf(v[j] - m);
        sum += v[j];
    }
    sr[tid] = sum;
    __syncthreads();
    for (int s = 128; s > 0; s >>= 1) {
        if (tid < s) sr[tid] += sr[tid + s];
        __syncthreads();
    }
    float inv = 1.f / sr[0];
#pragma unroll
    for (int j = 0; j < 8; j++) sal[j * 256 + tid] = v[j] * inv;
    __syncthreads();

    // --- weighted sum over this half's 8 t-subtiles ---
    const int c16 = tid & 7;
    const int rbase = tid >> 3;             // 0..31
    float acc[8];
#pragma unroll
    for (int j = 0; j < 8; j++) acc[j] = 0.f;

#pragma unroll 1
    for (int ii = 0; ii < 8; ii++) {
        const int i = half * 8 + ii;
        const char* tile = (const char*)g_encHT +
                           (((size_t)(b * 16 + i) * 16 + kt) << 14);
#pragma unroll
        for (int rg = 0; rg < 4; rg++) {
            int r = rbase + rg * 32;
            uint4 u = *(const uint4*)(tile + SW128((uint32_t)(r * 128 + c16 * 16)));
            float a = sal[i * 128 + r];
            float2 f0 = __half22float2(*(__half2*)&u.x);
            float2 f1 = __half22float2(*(__half2*)&u.y);
            float2 f2 = __half22float2(*(__half2*)&u.z);
            float2 f3 = __half22float2(*(__half2*)&u.w);
            acc[0] += a * f0.x; acc[1] += a * f0.y;
            acc[2] += a * f1.x; acc[3] += a * f1.y;
            acc[4] += a * f2.x; acc[5] += a * f2.y;
            acc[6] += a * f3.x; acc[7] += a * f3.y;
        }
    }
#pragma unroll
    for (int j = 0; j < 8; j++) red[c16 * 8 + j][rbase] = acc[j];
    __syncthreads();
    if (tid < 64) {
        float s = 0.f;
#pragma unroll
        for (int i = 0; i < 32; i++) s += red[tid][i];
        atomicAdd(&out[b * H_DIM + kt * 64 + tid], s);
    }
}

// ------------------------------- GEMM kernel -------------------------------
// R13/R10 GEMM; kt==0 sdp load folds the dp reduction (bias + 4 partials).
// Persistent 296 CTAs, 3-stage bulk-copy ring, empty-mbarrier ring, sdp/sw
// double-buffered, atomicAdd score partials.

__global__ void __launch_bounds__(GEMM_THREADS)
gemm_scores_kernel(const float* __restrict__ w_vec,
                   const float* __restrict__ bias) {
    extern __shared__ __align__(1024) char smem[];
    uint32_t sb = smem_u32(smem);
    const int tid = threadIdx.x;
    const int lane = tid & 31;
    const int wid = tid >> 5;
    const int warp_m = wid & 1;
    const int warp_n = wid >> 1;
    const int bid = blockIdx.x;

    float* sdp = (float*)(smem + OFF_DP);   // [2][128]
    float* sw = (float*)(smem + OFF_W);     // [2][128]
    float* sred = (float*)(smem + OFF_RED);

    const uint32_t mb_full = sb + OFF_MBAR;
    const uint32_t mb_empty = sb + OFF_MBAR + 32;

    uint32_t a_off[4];
#pragma unroll
    for (int mi = 0; mi < 4; mi++) {
        int ar = warp_m * 64 + mi * 16 + (lane & 15);
        a_off[mi] = SW128(ar * 128 + (lane >> 4) * 16);
    }
    const int b_row_in = (lane & 7) + ((lane >> 4) & 1) * 8;
    const uint32_t b_koff = ((lane >> 3) & 1) * 16;
    uint32_t b_off[4];
#pragma unroll
    for (int bg = 0; bg < 4; bg++) {
        int brow = warp_n * 64 + bg * 16 + b_row_in;
        b_off[bg] = SW128(brow * 128 + b_koff);
    }

    const char* encT = (const char*)g_encHT;
    const char* vtT = (const char*)g_VtHT;

    const int n_units = (NUM_UNITS - bid + GEMM_CTAS - 1) / GEMM_CTAS;
    const int total_stages = n_units * 32;

    if (tid == 0) {
#pragma unroll
        for (int b = 0; b < NSTAGES; b++) {
            mbar_init(mb_full + b * 8, 1);
            mbar_init(mb_empty + b * 8, 4);   // one arrive per warp
        }
    }
    __syncthreads();

#define STAGE_SRC(s, asrc, bsrc)                                          \
    {                                                                     \
        int u_ = bid + ((s) >> 5) * GEMM_CTAS;                            \
        int mtile_ = u_ >> 2;                                             \
        int loc_ = (s) & 31;                                              \
        int nc_ = (u_ & 3) * 2 + (loc_ >> 4);                             \
        int kt_ = loc_ & 15;                                              \
        asrc = encT + (((size_t)mtile_ * 16 + kt_) << 14);                \
        bsrc = vtT + (((size_t)nc_ * 16 + kt_) << 14);                    \
    }

    if (tid == 0) {
#pragma unroll
        for (int s = 0; s < NSTAGES - 1; s++) {
            const char *as_, *bs_;
            STAGE_SRC(s, as_, bs_);
            uint32_t mb = mb_full + s * 8;
            uint32_t dst = sb + s * STAGE_BYTES;
            mbar_expect_tx(mb, STAGE_BYTES);
            bulk_cp(dst, as_, 16384, mb);
            bulk_cp(dst + 16384, bs_, 16384, mb);
        }
    }

    float acc[4][8][4];
#pragma unroll
    for (int mi = 0; mi < 4; mi++)
#pragma unroll
        for (int ni = 0; ni < 8; ni++)
#pragma unroll
            for (int r = 0; r < 4; r++) acc[mi][ni][r] = 0.f;
    float p[8];
#pragma unroll
    for (int j = 0; j < 8; j++) p[j] = 0.f;

    uint32_t eph0 = 0, eph1 = 0, eph2 = 0;   // producer empty-phases

#pragma unroll 1
    for (int s = 0; s < total_stages; s++) {
        const int u = bid + (s >> 5) * GEMM_CTAS;
        const int mtile = u >> 2;
        const int loc = s & 31;
        const int nc = (u & 3) * 2 + (loc >> 4);
        const int kt = loc & 15;
        const int h = loc >> 4;            // sdp/sw buffer index
        const int bidx = mtile >> 4;

        if (tid == 0 && s + NSTAGES - 1 < total_stages) {
            const int sp = s + NSTAGES - 1;
            const int bb = sp % NSTAGES;
            if (sp >= NSTAGES) {           // buffer previously consumed
                if (bb == 0)      { mbar_wait(mb_empty + 0,  eph0); eph0 ^= 1; }
                else if (bb == 1) { mbar_wait(mb_empty + 8,  eph1); eph1 ^= 1; }
                else              { mbar_wait(mb_empty + 16, eph2); eph2 ^= 1; }
            }
            const char *as_, *bs_;
            STAGE_SRC(sp, as_, bs_);
            uint32_t mb = mb_full + bb * 8;
            uint32_t dst = sb + bb * STAGE_BYTES;
            mbar_expect_tx(mb, STAGE_BYTES);
            bulk_cp(dst, as_, 16384, mb);
            bulk_cp(dst + 16384, bs_, 16384, mb);
        }
        if (kt == 0) {
            int idx = bidx * C_DIM + nc * N_CHUNK + tid;
            sdp[h * 128 + tid] = bias[nc * N_CHUNK + tid] + g_dpp[0][idx] +
                                 g_dpp[1][idx] + g_dpp[2][idx] + g_dpp[3][idx];
            sw[h * 128 + tid] = w_vec[nc * N_CHUNK + tid];
        }
        mbar_wait(mb_full + (s % NSTAGES) * 8, (s / NSTAGES) & 1);

        uint32_t stA = sb + (s % NSTAGES) * STAGE_BYTES;
        uint32_t stB = stA + 16384;
#pragma unroll
        for (int ks = 0; ks < 4; ks++) {
            const uint32_t kx = (uint32_t)(ks * 32);
            uint32_t af[4][4];
#pragma unroll
            for (int mi = 0; mi < 4; mi++)
                ldsm4(af[mi][0], af[mi][1], af[mi][2], af[mi][3],
                      stA + (a_off[mi] ^ kx));
            uint32_t bf[4][4];
#pragma unroll
            for (int bg = 0; bg < 4; bg++)
                ldsm4(bf[bg][0], bf[bg][1], bf[bg][2], bf[bg][3],
                      stB + (b_off[bg] ^ kx));
            if (ks == 3 && lane == 0)      // last smem read of this stage done
                mbar_arrive(mb_empty + (s % NSTAGES) * 8);
#pragma unroll
            for (int mi = 0; mi < 4; mi++)
#pragma unroll
                for (int ni = 0; ni < 8; ni++) {
                    int bg = ni >> 1, sub = (ni & 1) * 2;
                    mma16816(acc[mi][ni], af[mi][0], af[mi][1], af[mi][2],
                             af[mi][3], bf[bg][sub], bf[bg][sub + 1]);
                }
        }

        if (kt == 15) {
#pragma unroll
            for (int mi = 0; mi < 4; mi++)
#pragma unroll
                for (int ni = 0; ni < 8; ni++) {
                    int col = warp_n * 64 + ni * 8 + (lane & 3) * 2;
                    float d0 = sdp[h * 128 + col], d1 = sdp[h * 128 + col + 1];
                    float w0 = sw[h * 128 + col], w1 = sw[h * 128 + col + 1];
                    float* c = acc[mi][ni];
                    p[mi * 2 + 0] += tanh_ap(c[0] + d0) * w0 + tanh_ap(c[1] + d1) * w1;
                    p[mi * 2 + 1] += tanh_ap(c[2] + d0) * w0 + tanh_ap(c[3] + d1) * w1;
                    c[0] = 0.f; c[1] = 0.f; c[2] = 0.f; c[3] = 0.f;
                }
        }
        if (loc == 31) {
#pragma unroll
            for (int j = 0; j < 8; j++) {
                p[j] += __shfl_xor_sync(0xFFFFFFFF, p[j], 1);
                p[j] += __shfl_xor_sync(0xFFFFFFFF, p[j], 2);
            }
            if (warp_n == 0 && (lane & 3) == 0) {
#pragma unroll
                for (int j = 0; j < 8; j++) {
                    int row = warp_m * 64 + (j >> 1) * 16 + (j & 1) * 8 + (lane >> 2);
                    sred[row] = p[j];
                }
            }
            __syncthreads();
            if (warp_n == 1 && (lane & 3) == 0) {
#pragma unroll
                for (int j = 0; j < 8; j++) {
                    int row = warp_m * 64 + (j >> 1) * 16 + (j & 1) * 8 + (lane >> 2);
                    sred[row] += p[j];
                }
            }
            __syncthreads();
            atomicAdd(&g_scores[mtile * CTA_M + tid], sred[tid]);
#pragma unroll
            for (int j = 0; j < 8; j++) p[j] = 0.f;
        }
    }
#undef STAGE_SRC
}

// -------------------------------- launcher ---------------------------------

extern "C" void kernel_launch(void* const* d_in, const int* in_sizes, int n_in,
                              void* d_out, int out_size) {
    const float* dec  = (const float*)d_in[0];
    const float* enc  = (const float*)d_in[1];
    const float* W    = (const float*)d_in[2];
    const float* V    = (const float*)d_in[3];
    const float* bias = (const float*)d_in[4];
    const float* w    = (const float*)d_in[5];
    float* out = (float*)d_out;

    cudaFuncSetAttribute(gemm_scores_kernel,
                         cudaFuncAttributeMaxDynamicSharedMemorySize, SMEM_TOTAL);

    prep_kernel<<<PREP_BLOCKS, 256>>>(enc, V, out);                   // 1
    dp_part_kernel<<<dim3(8, 4), 128>>>(dec, W);                      // 2
    gemm_scores_kernel<<<GEMM_CTAS, GEMM_THREADS, SMEM_TOTAL>>>(w, bias);  // 3
    context_kernel<<<dim3(16, 32, 2), 256>>>(out);                    // 4
}